// round 2
// baseline (speedup 1.0000x reference)
#include <cuda_runtime.h>
#include <math.h>

#define NT 2
#define NN 50000
#define EE 400000
#define CC 128
#define HH 4
#define DD 32

// ---------------- device scratch (allocation-free: static globals) ----------------
__device__ float g_q  [NT][(size_t)NN*CC];
__device__ float g_k  [NT][(size_t)NN*CC];   // k_rel (a_rel, p_rel, scale folded into weights)
__device__ float g_v  [NT][(size_t)NN*CC];   // v_rel (m_rel folded into weights)
__device__ float g_agg[NT][(size_t)NN*CC];
__device__ float g_o  [NT][(size_t)NN*CC];
__device__ float g_xb [NT][(size_t)NN*CC];   // x ping buffer between layers
__device__ float g_att[NT][(size_t)EE*HH];
__device__ float g_den[NT][(size_t)NN*HH];
__device__ float g_WkF[NT][CC*CC];
__device__ float g_WvF[NT][CC*CC];
__device__ float g_bkF[NT][CC];
__device__ float g_bvF[NT][CC];

__device__ __forceinline__ float gelu_tanh(float v) {
    const float c = 0.7978845608028654f;
    float t = tanhf(c * (v + 0.044715f * v * v * v));
    return 0.5f * v * (1.0f + t);
}

// ---------------- fold a_rel/m_rel (+ p_rel*scale) into K/V projection weights ----
// g_WkF[t] = Wk[l,t] @ blockdiag_h(a_rel[l,t,h] * p_rel[l,t,h] * 1/sqrt(D))
// g_WvF[t] = Wv[l,t] @ blockdiag_h(m_rel[l,t,h])
__global__ void fold_weights(const float* __restrict__ Wk, const float* __restrict__ bk,
                             const float* __restrict__ Wv, const float* __restrict__ bv,
                             const float* __restrict__ a_rel, const float* __restrict__ m_rel,
                             const float* __restrict__ p_rel, int l)
{
    int t = blockIdx.x;         // node/edge type (st == e under META)
    int which = blockIdx.y;     // 0 = K (a_rel), 1 = V (m_rel)
    const float* W = which ? Wv : Wk;
    const float* B = which ? bv : bk;
    const float* R = which ? m_rel : a_rel;

    __shared__ float sA[HH * DD * DD];  // [h][d][f]
    int tid = threadIdx.x;              // 128 threads
    const float* Rl = R + (size_t)(l * NT + t) * (HH * DD * DD);
    for (int i = tid; i < HH * DD * DD; i += 128) {
        int h = i >> 10;
        float sc = which ? 1.0f
                         : p_rel[(l * NT + t) * HH + h] * 0.17677669529663687f; // 1/sqrt(32)
        sA[i] = Rl[i] * sc;
    }
    __syncthreads();

    int h = tid >> 5, f = tid & 31;     // output column c' = h*32+f == tid
    const float* Wb = W + (size_t)(l * NT + t) * CC * CC;
    float* Wo = which ? g_WvF[t] : g_WkF[t];
    for (int c = 0; c < CC; c++) {
        const float* wr = Wb + c * CC + h * DD;
        const float* ar = sA + h * DD * DD + f;
        float s = 0.f;
        #pragma unroll 8
        for (int d = 0; d < DD; d++) s += wr[d] * ar[d * DD];
        Wo[c * CC + tid] = s;
    }
    {
        const float* br = B + (size_t)(l * NT + t) * CC + h * DD;
        const float* ar = sA + h * DD * DD + f;
        float s = 0.f;
        #pragma unroll 8
        for (int d = 0; d < DD; d++) s += br[d] * ar[d * DD];
        (which ? g_bvF : g_bkF)[t][tid] = s;
    }
}

// ---------------- fp32 GEMM: Y[n,128] = act(X[n,128]) @ W[128,128] + b -------------
// BM=64 rows/block, full N=128, full K=128 in smem. 256 threads: 8x4 microtile.
__global__ void gemm128(const float* __restrict__ X, const float* __restrict__ W,
                        const float* __restrict__ bias, float* __restrict__ Y,
                        int nrows, int apply_gelu)
{
    extern __shared__ float smem[];
    float* sX = smem;            // 64*128
    float* sW = smem + 64 * 128; // 128*128
    int tid = threadIdx.x;
    int row0 = blockIdx.x * 64;

    const float4* W4 = (const float4*)W;
    float4* sW4v = (float4*)sW;
    #pragma unroll
    for (int i = 0; i < 16; i++) sW4v[tid + i * 256] = W4[tid + i * 256];

    int rows = nrows - row0; if (rows > 64) rows = 64;
    int maxv = rows * 32;
    const float4* X4 = (const float4*)(X + (size_t)row0 * 128);
    float4* sX4v = (float4*)sX;
    #pragma unroll
    for (int i = 0; i < 8; i++) {
        int idx = tid + i * 256;
        float4 v = make_float4(0.f, 0.f, 0.f, 0.f);
        if (idx < maxv) v = X4[idx];
        if (apply_gelu) {
            v.x = gelu_tanh(v.x); v.y = gelu_tanh(v.y);
            v.z = gelu_tanh(v.z); v.w = gelu_tanh(v.w);
        }
        sX4v[idx] = v;
    }
    __syncthreads();

    int tx = tid & 31, ty = tid >> 5;
    float acc[8][4];
    #pragma unroll
    for (int i = 0; i < 8; i++)
        #pragma unroll
        for (int j = 0; j < 4; j++) acc[i][j] = 0.f;

    const float4* sW4 = (const float4*)sW;
    const float4* sX4 = (const float4*)sX;
    #pragma unroll 4
    for (int k4 = 0; k4 < 32; k4++) {
        float4 w0 = sW4[(k4 * 4 + 0) * 32 + tx];
        float4 w1 = sW4[(k4 * 4 + 1) * 32 + tx];
        float4 w2 = sW4[(k4 * 4 + 2) * 32 + tx];
        float4 w3 = sW4[(k4 * 4 + 3) * 32 + tx];
        #pragma unroll
        for (int i = 0; i < 8; i++) {
            float4 xv = sX4[(ty * 8 + i) * 32 + k4];
            acc[i][0] += xv.x * w0.x + xv.y * w1.x + xv.z * w2.x + xv.w * w3.x;
            acc[i][1] += xv.x * w0.y + xv.y * w1.y + xv.z * w2.y + xv.w * w3.y;
            acc[i][2] += xv.x * w0.z + xv.y * w1.z + xv.z * w2.z + xv.w * w3.z;
            acc[i][3] += xv.x * w0.w + xv.y * w1.w + xv.z * w2.w + xv.w * w3.w;
        }
    }

    float4 b4 = ((const float4*)bias)[tx];
    #pragma unroll
    for (int i = 0; i < 8; i++) {
        int r = row0 + ty * 8 + i;
        if (r < nrows) {
            float4 o;
            o.x = acc[i][0] + b4.x; o.y = acc[i][1] + b4.y;
            o.z = acc[i][2] + b4.z; o.w = acc[i][3] + b4.w;
            ((float4*)(Y + (size_t)r * 128))[tx] = o;
        }
    }
}

// ---------------- edge pass 1: logits -> exp, accumulate denominator --------------
// warp per edge. Softmax-max subtraction dropped (logits O(1); value-identical).
// NOTE: edge_index is int32 on device (JAX default x64-disabled downcasts int64).
__global__ void edge_att(const int* __restrict__ ei)
{
    int e = blockIdx.y;
    int id = blockIdx.x * 8 + (threadIdx.x >> 5);
    if (id >= EE) return;
    int lane = threadIdx.x & 31;
    int si = ei[(size_t)(e * 2 + 0) * EE + id];
    int di = ei[(size_t)(e * 2 + 1) * EE + id];
    int st = e, dt = 1 - e;

    float4 kv = ((const float4*)(g_k[st] + (size_t)si * CC))[lane];
    float4 qv = ((const float4*)(g_q[dt] + (size_t)di * CC))[lane];
    float s = kv.x * qv.x + kv.y * qv.y + kv.z * qv.z + kv.w * qv.w;
    s += __shfl_xor_sync(0xffffffffu, s, 1);
    s += __shfl_xor_sync(0xffffffffu, s, 2);
    s += __shfl_xor_sync(0xffffffffu, s, 4);
    float a = expf(s);
    if ((lane & 7) == 0) {
        int h = lane >> 3;
        g_att[e][(size_t)id * HH + h] = a;
        atomicAdd(&g_den[dt][(size_t)di * HH + h], a);
    }
}

// ---------------- edge pass 2: weighted V scatter ----------------------------------
__global__ void edge_agg(const int* __restrict__ ei)
{
    int e = blockIdx.y;
    int id = blockIdx.x * 8 + (threadIdx.x >> 5);
    if (id >= EE) return;
    int lane = threadIdx.x & 31;
    int si = ei[(size_t)(e * 2 + 0) * EE + id];
    int di = ei[(size_t)(e * 2 + 1) * EE + id];
    int st = e, dt = 1 - e;

    int h = lane >> 3;
    float a = g_att[e][(size_t)id * HH + h];
    float den = g_den[dt][(size_t)di * HH + h];
    float w = a / (den + 1e-16f);
    float4 vv = ((const float4*)(g_v[st] + (size_t)si * CC))[lane];
    float* dst = g_agg[dt] + (size_t)di * CC + lane * 4;
    atomicAdd(dst + 0, w * vv.x);
    atomicAdd(dst + 1, w * vv.y);
    atomicAdd(dst + 2, w * vv.z);
    atomicAdd(dst + 3, w * vv.w);
}

// ---------------- gated skip + LayerNorm + ReLU ------------------------------------
__global__ void post_ln(const float* __restrict__ o, const float* __restrict__ xin,
                        float* __restrict__ xout, float* __restrict__ dout,
                        const float* __restrict__ skip, const float* __restrict__ lng,
                        const float* __restrict__ lnb, int l)
{
    int t = blockIdx.y;
    int warp = threadIdx.x >> 5, lane = threadIdx.x & 31;
    int n = blockIdx.x * 8 + warp;
    if (n >= NN) return;
    size_t base = ((size_t)t * NN + n) * CC;

    float4 o4 = ((const float4*)(o + base))[lane];
    float4 x4 = ((const float4*)(xin + base))[lane];
    float beta = 1.f / (1.f + expf(-skip[l * NT + t]));
    float4 v;
    v.x = beta * o4.x + (1.f - beta) * x4.x;
    v.y = beta * o4.y + (1.f - beta) * x4.y;
    v.z = beta * o4.z + (1.f - beta) * x4.z;
    v.w = beta * o4.w + (1.f - beta) * x4.w;

    float s  = v.x + v.y + v.z + v.w;
    float sq = v.x * v.x + v.y * v.y + v.z * v.z + v.w * v.w;
    #pragma unroll
    for (int m = 16; m; m >>= 1) {
        s  += __shfl_xor_sync(0xffffffffu, s,  m);
        sq += __shfl_xor_sync(0xffffffffu, sq, m);
    }
    float mu  = s * (1.f / 128.f);
    float var = sq * (1.f / 128.f) - mu * mu;
    float inv = rsqrtf(var + 1e-5f);

    float4 g4 = ((const float4*)(lng + (size_t)(l * NT + t) * CC))[lane];
    float4 b4 = ((const float4*)(lnb + (size_t)(l * NT + t) * CC))[lane];
    float4 y;
    y.x = fmaxf((v.x - mu) * inv * g4.x + b4.x, 0.f);
    y.y = fmaxf((v.y - mu) * inv * g4.y + b4.y, 0.f);
    y.z = fmaxf((v.z - mu) * inv * g4.z + b4.z, 0.f);
    y.w = fmaxf((v.w - mu) * inv * g4.w + b4.w, 0.f);
    ((float4*)(xout + base))[lane] = y;
    if (dout != nullptr && t == 0)
        ((float4*)(dout + (size_t)n * CC))[lane] = y;
}

// ---------------- host orchestration ------------------------------------------------
extern "C" void kernel_launch(void* const* d_in, const int* in_sizes, int n_in,
                              void* d_out, int out_size)
{
    const float* x     = (const float*)d_in[0];
    const int*   ei    = (const int*)d_in[1];   // int32 on device (JAX x64 disabled)
    const float* Wk    = (const float*)d_in[2];
    const float* bk    = (const float*)d_in[3];
    const float* Wq    = (const float*)d_in[4];
    const float* bq    = (const float*)d_in[5];
    const float* Wv    = (const float*)d_in[6];
    const float* bv    = (const float*)d_in[7];
    const float* Wa    = (const float*)d_in[8];
    const float* ba    = (const float*)d_in[9];
    const float* skip  = (const float*)d_in[10];
    const float* a_rel = (const float*)d_in[11];
    const float* m_rel = (const float*)d_in[12];
    const float* p_rel = (const float*)d_in[13];
    const float* ln_g  = (const float*)d_in[14];
    const float* ln_b  = (const float*)d_in[15];
    float* out = (float*)d_out;

    void *pq, *pk, *pv, *pagg, *po, *pxb, *pden, *pWkF, *pWvF, *pbkF, *pbvF;
    cudaGetSymbolAddress(&pq,   g_q);
    cudaGetSymbolAddress(&pk,   g_k);
    cudaGetSymbolAddress(&pv,   g_v);
    cudaGetSymbolAddress(&pagg, g_agg);
    cudaGetSymbolAddress(&po,   g_o);
    cudaGetSymbolAddress(&pxb,  g_xb);
    cudaGetSymbolAddress(&pden, g_den);
    cudaGetSymbolAddress(&pWkF, g_WkF);
    cudaGetSymbolAddress(&pWvF, g_WvF);
    cudaGetSymbolAddress(&pbkF, g_bkF);
    cudaGetSymbolAddress(&pbvF, g_bvF);

    const int SMEM = (64 * 128 + 128 * 128) * 4;  // 96 KB
    cudaFuncSetAttribute(gemm128, cudaFuncAttributeMaxDynamicSharedMemorySize, SMEM);

    dim3 gemm_grid((NN + 63) / 64);
    dim3 edge_grid(EE / 8, 2);
    dim3 ln_grid((NN + 7) / 8, 2);

    for (int l = 0; l < 2; l++) {
        const float* xin = (l == 0) ? x : (const float*)pxb;

        cudaMemsetAsync(pagg, 0, sizeof(float) * (size_t)NT * NN * CC);
        cudaMemsetAsync(pden, 0, sizeof(float) * (size_t)NT * NN * HH);

        fold_weights<<<dim3(2, 2), 128>>>(Wk, bk, Wv, bv, a_rel, m_rel, p_rel, l);

        for (int t = 0; t < 2; t++) {
            const float* X = xin + (size_t)t * NN * CC;
            gemm128<<<gemm_grid, 256, SMEM>>>(
                X, Wq + (size_t)(l * NT + t) * CC * CC, bq + (size_t)(l * NT + t) * CC,
                (float*)pq + (size_t)t * NN * CC, NN, 0);
            gemm128<<<gemm_grid, 256, SMEM>>>(
                X, (const float*)pWkF + (size_t)t * CC * CC, (const float*)pbkF + (size_t)t * CC,
                (float*)pk + (size_t)t * NN * CC, NN, 0);
            gemm128<<<gemm_grid, 256, SMEM>>>(
                X, (const float*)pWvF + (size_t)t * CC * CC, (const float*)pbvF + (size_t)t * CC,
                (float*)pv + (size_t)t * NN * CC, NN, 0);
        }

        edge_att<<<edge_grid, 256>>>(ei);
        edge_agg<<<edge_grid, 256>>>(ei);

        for (int t = 0; t < 2; t++) {
            gemm128<<<gemm_grid, 256, SMEM>>>(
                (const float*)pagg + (size_t)t * NN * CC,
                Wa + (size_t)(l * NT + t) * CC * CC, ba + (size_t)(l * NT + t) * CC,
                (float*)po + (size_t)t * NN * CC, NN, 1);
        }

        post_ln<<<ln_grid, 256>>>((const float*)po, xin, (float*)pxb,
                                  (l == 1) ? out : nullptr, skip, ln_g, ln_b, l);
    }
}

// round 3
// speedup vs baseline: 1.3432x; 1.3432x over previous
#include <cuda_runtime.h>
#include <math.h>

#define NT 2
#define NN 50000
#define EE 400000
#define CC 128
#define HH 4
#define DD 32

// ---------------- device scratch (allocation-free: static globals) ----------------
__device__ float g_q  [NT][(size_t)NN*CC];
__device__ float g_k  [NT][(size_t)NN*CC];   // k_rel (a_rel, p_rel, scale folded into weights)
__device__ float g_v  [NT][(size_t)NN*CC];   // v_rel (m_rel folded into weights)
__device__ float g_agg[NT][(size_t)NN*CC];   // UNNORMALIZED sum of a*v (divided by den in Wa GEMM)
__device__ float g_o  [NT][(size_t)NN*CC];
__device__ float g_xb [NT][(size_t)NN*CC];   // x ping buffer between layers
__device__ float g_den[NT][(size_t)NN*HH];
__device__ float g_WkF[NT][CC*CC];
__device__ float g_WvF[NT][CC*CC];
__device__ float g_bkF[NT][CC];
__device__ float g_bvF[NT][CC];

__device__ __forceinline__ float gelu_tanh(float v) {
    const float c = 0.7978845608028654f;
    float t = tanhf(c * (v + 0.044715f * v * v * v));
    return 0.5f * v * (1.0f + t);
}

__device__ __forceinline__ void red_add_v4(float* p, float a, float b, float c, float d) {
    asm volatile("red.global.add.v4.f32 [%0], {%1, %2, %3, %4};"
                 :: "l"(p), "f"(a), "f"(b), "f"(c), "f"(d) : "memory");
}

// ---------------- fold a_rel/m_rel (+ p_rel*scale) into K/V projection weights ----
__global__ void fold_weights(const float* __restrict__ Wk, const float* __restrict__ bk,
                             const float* __restrict__ Wv, const float* __restrict__ bv,
                             const float* __restrict__ a_rel, const float* __restrict__ m_rel,
                             const float* __restrict__ p_rel, int l)
{
    int t = blockIdx.x;         // node/edge type (st == e under META)
    int which = blockIdx.y;     // 0 = K (a_rel), 1 = V (m_rel)
    const float* W = which ? Wv : Wk;
    const float* B = which ? bv : bk;
    const float* R = which ? m_rel : a_rel;

    __shared__ float sA[HH * DD * DD];  // [h][d][f]
    int tid = threadIdx.x;              // 128 threads
    const float* Rl = R + (size_t)(l * NT + t) * (HH * DD * DD);
    for (int i = tid; i < HH * DD * DD; i += 128) {
        int h = i >> 10;
        float sc = which ? 1.0f
                         : p_rel[(l * NT + t) * HH + h] * 0.17677669529663687f; // 1/sqrt(32)
        sA[i] = Rl[i] * sc;
    }
    __syncthreads();

    int h = tid >> 5, f = tid & 31;     // output column c' = h*32+f == tid
    const float* Wb = W + (size_t)(l * NT + t) * CC * CC;
    float* Wo = which ? g_WvF[t] : g_WkF[t];
    for (int c = 0; c < CC; c++) {
        const float* wr = Wb + c * CC + h * DD;
        const float* ar = sA + h * DD * DD + f;
        float s = 0.f;
        #pragma unroll 8
        for (int d = 0; d < DD; d++) s += wr[d] * ar[d * DD];
        Wo[c * CC + tid] = s;
    }
    {
        const float* br = B + (size_t)(l * NT + t) * CC + h * DD;
        const float* ar = sA + h * DD * DD + f;
        float s = 0.f;
        #pragma unroll 8
        for (int d = 0; d < DD; d++) s += br[d] * ar[d * DD];
        (which ? g_bvF : g_bkF)[t][tid] = s;
    }
}

// ---------------- fp32 GEMM body: Y[n,128] = act(X[n,128] / den) @ W[128,128] + b --
// BM=64 rows/block, full N=128, full K=128 in smem. 256 threads: 8x4 microtile.
__device__ __forceinline__ void gemm_body(const float* __restrict__ X,
                                          const float* __restrict__ W,
                                          const float* __restrict__ bias,
                                          float* __restrict__ Y,
                                          int nrows, int apply_gelu,
                                          const float* __restrict__ den,
                                          float* smem)
{
    float* sX = smem;            // 64*128
    float* sW = smem + 64 * 128; // 128*128
    int tid = threadIdx.x;
    int row0 = blockIdx.x * 64;

    const float4* W4 = (const float4*)W;
    float4* sW4v = (float4*)sW;
    #pragma unroll
    for (int i = 0; i < 16; i++) sW4v[tid + i * 256] = W4[tid + i * 256];

    int rows = nrows - row0; if (rows > 64) rows = 64;
    int maxv = rows * 32;
    const float4* X4 = (const float4*)(X + (size_t)row0 * 128);
    float4* sX4v = (float4*)sX;
    #pragma unroll
    for (int i = 0; i < 8; i++) {
        int idx = tid + i * 256;
        float4 v = make_float4(0.f, 0.f, 0.f, 0.f);
        if (idx < maxv) v = X4[idx];
        if (den) {
            int rl = idx >> 5, h = (idx & 31) >> 3;
            float d = den[(size_t)(row0 + rl) * HH + h];
            float invd = 1.f / (d + 1e-16f);
            v.x *= invd; v.y *= invd; v.z *= invd; v.w *= invd;
        }
        if (apply_gelu) {
            v.x = gelu_tanh(v.x); v.y = gelu_tanh(v.y);
            v.z = gelu_tanh(v.z); v.w = gelu_tanh(v.w);
        }
        sX4v[idx] = v;
    }
    __syncthreads();

    int tx = tid & 31, ty = tid >> 5;
    float acc[8][4];
    #pragma unroll
    for (int i = 0; i < 8; i++)
        #pragma unroll
        for (int j = 0; j < 4; j++) acc[i][j] = 0.f;

    const float4* sW4 = (const float4*)sW;
    const float4* sX4 = (const float4*)sX;
    #pragma unroll 4
    for (int k4 = 0; k4 < 32; k4++) {
        float4 w0 = sW4[(k4 * 4 + 0) * 32 + tx];
        float4 w1 = sW4[(k4 * 4 + 1) * 32 + tx];
        float4 w2 = sW4[(k4 * 4 + 2) * 32 + tx];
        float4 w3 = sW4[(k4 * 4 + 3) * 32 + tx];
        #pragma unroll
        for (int i = 0; i < 8; i++) {
            float4 xv = sX4[(ty * 8 + i) * 32 + k4];
            acc[i][0] += xv.x * w0.x + xv.y * w1.x + xv.z * w2.x + xv.w * w3.x;
            acc[i][1] += xv.x * w0.y + xv.y * w1.y + xv.z * w2.y + xv.w * w3.y;
            acc[i][2] += xv.x * w0.z + xv.y * w1.z + xv.z * w2.z + xv.w * w3.z;
            acc[i][3] += xv.x * w0.w + xv.y * w1.w + xv.z * w2.w + xv.w * w3.w;
        }
    }

    float4 b4 = ((const float4*)bias)[tx];
    #pragma unroll
    for (int i = 0; i < 8; i++) {
        int r = row0 + ty * 8 + i;
        if (r < nrows) {
            float4 o;
            o.x = acc[i][0] + b4.x; o.y = acc[i][1] + b4.y;
            o.z = acc[i][2] + b4.z; o.w = acc[i][3] + b4.w;
            ((float4*)(Y + (size_t)r * 128))[tx] = o;
        }
    }
}

// QKV fused launch: blockIdx.y = {Q,K,V}, blockIdx.z = node type.
__global__ void gemm_qkv(const float* __restrict__ Xbase,
                         const float* __restrict__ Wq_l, const float* __restrict__ bq_l)
{
    extern __shared__ float smem[];
    int t = blockIdx.z;
    const float* X = Xbase + (size_t)t * NN * CC;
    const float* W; const float* B; float* Y;
    if (blockIdx.y == 0)      { W = Wq_l + (size_t)t * CC * CC; B = bq_l + (size_t)t * CC; Y = g_q[t]; }
    else if (blockIdx.y == 1) { W = g_WkF[t]; B = g_bkF[t]; Y = g_k[t]; }
    else                      { W = g_WvF[t]; B = g_bvF[t]; Y = g_v[t]; }
    gemm_body(X, W, B, Y, NN, 0, nullptr, smem);
}

// Wa epilogue GEMM: normalize by den, GELU, project. blockIdx.z = node type.
__global__ void gemm_wa(const float* __restrict__ Wa_l, const float* __restrict__ ba_l)
{
    extern __shared__ float smem[];
    int t = blockIdx.z;
    gemm_body(g_agg[t], Wa_l + (size_t)t * CC * CC, ba_l + (size_t)t * CC,
              g_o[t], NN, 1, g_den[t], smem);
}

// ---------------- fused edge pass: logits -> exp -> den + unnormalized V scatter ---
// warp per edge. Softmax-max subtraction dropped (logits O(1); value-identical).
__global__ void edge_fused(const int* __restrict__ ei)
{
    int e = blockIdx.y;
    int id = blockIdx.x * 8 + (threadIdx.x >> 5);
    if (id >= EE) return;
    int lane = threadIdx.x & 31;
    int si = ei[(size_t)(e * 2 + 0) * EE + id];
    int di = ei[(size_t)(e * 2 + 1) * EE + id];
    int st = e, dt = 1 - e;

    float4 kv = ((const float4*)(g_k[st] + (size_t)si * CC))[lane];
    float4 qv = ((const float4*)(g_q[dt] + (size_t)di * CC))[lane];
    float s = kv.x * qv.x + kv.y * qv.y + kv.z * qv.z + kv.w * qv.w;
    s += __shfl_xor_sync(0xffffffffu, s, 1);
    s += __shfl_xor_sync(0xffffffffu, s, 2);
    s += __shfl_xor_sync(0xffffffffu, s, 4);
    float a = expf(s);                 // all 8 lanes of the head group hold a
    if ((lane & 7) == 0)
        atomicAdd(&g_den[dt][(size_t)di * HH + (lane >> 3)], a);

    float4 vv = ((const float4*)(g_v[st] + (size_t)si * CC))[lane];
    float* dst = g_agg[dt] + (size_t)di * CC + lane * 4;
    red_add_v4(dst, a * vv.x, a * vv.y, a * vv.z, a * vv.w);
}

// ---------------- gated skip + LayerNorm + ReLU ------------------------------------
__global__ void post_ln(const float* __restrict__ o, const float* __restrict__ xin,
                        float* __restrict__ xout, float* __restrict__ dout,
                        const float* __restrict__ skip, const float* __restrict__ lng,
                        const float* __restrict__ lnb, int l)
{
    int t = blockIdx.y;
    int warp = threadIdx.x >> 5, lane = threadIdx.x & 31;
    int n = blockIdx.x * 8 + warp;
    if (n >= NN) return;
    size_t base = ((size_t)t * NN + n) * CC;

    float4 o4 = ((const float4*)(o + base))[lane];
    float4 x4 = ((const float4*)(xin + base))[lane];
    float beta = 1.f / (1.f + expf(-skip[l * NT + t]));
    float4 v;
    v.x = beta * o4.x + (1.f - beta) * x4.x;
    v.y = beta * o4.y + (1.f - beta) * x4.y;
    v.z = beta * o4.z + (1.f - beta) * x4.z;
    v.w = beta * o4.w + (1.f - beta) * x4.w;

    float s  = v.x + v.y + v.z + v.w;
    float sq = v.x * v.x + v.y * v.y + v.z * v.z + v.w * v.w;
    #pragma unroll
    for (int m = 16; m; m >>= 1) {
        s  += __shfl_xor_sync(0xffffffffu, s,  m);
        sq += __shfl_xor_sync(0xffffffffu, sq, m);
    }
    float mu  = s * (1.f / 128.f);
    float var = sq * (1.f / 128.f) - mu * mu;
    float inv = rsqrtf(var + 1e-5f);

    float4 g4 = ((const float4*)(lng + (size_t)(l * NT + t) * CC))[lane];
    float4 b4 = ((const float4*)(lnb + (size_t)(l * NT + t) * CC))[lane];
    float4 y;
    y.x = fmaxf((v.x - mu) * inv * g4.x + b4.x, 0.f);
    y.y = fmaxf((v.y - mu) * inv * g4.y + b4.y, 0.f);
    y.z = fmaxf((v.z - mu) * inv * g4.z + b4.z, 0.f);
    y.w = fmaxf((v.w - mu) * inv * g4.w + b4.w, 0.f);
    ((float4*)(xout + base))[lane] = y;
    if (dout != nullptr && t == 0)
        ((float4*)(dout + (size_t)n * CC))[lane] = y;
}

// ---------------- host orchestration ------------------------------------------------
extern "C" void kernel_launch(void* const* d_in, const int* in_sizes, int n_in,
                              void* d_out, int out_size)
{
    const float* x     = (const float*)d_in[0];
    const int*   ei    = (const int*)d_in[1];   // int32 on device (JAX x64 disabled)
    const float* Wk    = (const float*)d_in[2];
    const float* bk    = (const float*)d_in[3];
    const float* Wq    = (const float*)d_in[4];
    const float* bq    = (const float*)d_in[5];
    const float* Wv    = (const float*)d_in[6];
    const float* bv    = (const float*)d_in[7];
    const float* Wa    = (const float*)d_in[8];
    const float* ba    = (const float*)d_in[9];
    const float* skip  = (const float*)d_in[10];
    const float* a_rel = (const float*)d_in[11];
    const float* m_rel = (const float*)d_in[12];
    const float* p_rel = (const float*)d_in[13];
    const float* ln_g  = (const float*)d_in[14];
    const float* ln_b  = (const float*)d_in[15];
    float* out = (float*)d_out;

    void *pagg, *pxb, *pden;
    cudaGetSymbolAddress(&pagg, g_agg);
    cudaGetSymbolAddress(&pxb,  g_xb);
    cudaGetSymbolAddress(&pden, g_den);
    void* po; cudaGetSymbolAddress(&po, g_o);

    const int SMEM = (64 * 128 + 128 * 128) * 4;  // 96 KB
    cudaFuncSetAttribute(gemm_qkv, cudaFuncAttributeMaxDynamicSharedMemorySize, SMEM);
    cudaFuncSetAttribute(gemm_wa,  cudaFuncAttributeMaxDynamicSharedMemorySize, SMEM);

    dim3 qkv_grid((NN + 63) / 64, 3, 2);
    dim3 wa_grid((NN + 63) / 64, 1, 2);
    dim3 edge_grid(EE / 8, 2);
    dim3 ln_grid((NN + 7) / 8, 2);

    for (int l = 0; l < 2; l++) {
        const float* xin = (l == 0) ? x : (const float*)pxb;

        cudaMemsetAsync(pagg, 0, sizeof(float) * (size_t)NT * NN * CC);
        cudaMemsetAsync(pden, 0, sizeof(float) * (size_t)NT * NN * HH);

        fold_weights<<<dim3(2, 2), 128>>>(Wk, bk, Wv, bv, a_rel, m_rel, p_rel, l);

        gemm_qkv<<<qkv_grid, 256, SMEM>>>(xin,
                                          Wq + (size_t)l * NT * CC * CC,
                                          bq + (size_t)l * NT * CC);

        edge_fused<<<edge_grid, 256>>>(ei);

        gemm_wa<<<wa_grid, 256, SMEM>>>(Wa + (size_t)l * NT * CC * CC,
                                        ba + (size_t)l * NT * CC);

        post_ln<<<ln_grid, 256>>>((const float*)po, xin, (float*)pxb,
                                  (l == 1) ? out : nullptr, skip, ln_g, ln_b, l);
    }
}

// round 5
// speedup vs baseline: 1.6371x; 1.2188x over previous
#include <cuda_runtime.h>
#include <cuda_bf16.h>
#include <math.h>
#include <stdint.h>

#define NT 2
#define NN 50000
#define EE 400000
#define CC 128
#define HH 4
#define DD 32
#define NTILES 391   // ceil(50000/128)

// ---------------- device scratch (allocation-free: static globals) ----------------
__device__ float g_q  [NT][(size_t)NN*CC];
__device__ float g_k  [NT][(size_t)NN*CC];
__device__ float g_v  [NT][(size_t)NN*CC];
__device__ float g_agg[NT][(size_t)NN*CC];   // UNNORMALIZED sum of a*v
__device__ float g_o  [NT][(size_t)NN*CC];
__device__ float g_xb [NT][(size_t)NN*CC];
__device__ float g_den[NT][(size_t)NN*HH];
// W in mma B-fragment order: [inst][ (ks*16+j)*32+lane ] = {hi_b0,hi_b1,lo_b0,lo_b1}
// inst: t*3+{Q,K,V} for t=0,1 ; 6+t for Wa
__device__ uint4 g_Wf  [8][4096];
__device__ float g_bias[8][CC];

// ---------------- small helpers ----------------------------------------------------
__device__ __forceinline__ uint32_t smem_u32(const void* p) {
    uint32_t a;
    asm("{ .reg .u64 t; cvta.to.shared.u64 t, %1; cvt.u32.u64 %0, t; }" : "=r"(a) : "l"(p));
    return a;
}
__device__ __forceinline__ float gelu_tanh(float v) {
    const float c = 0.7978845608028654f;
    float t = tanhf(c * (v + 0.044715f * v * v * v));
    return 0.5f * v * (1.0f + t);
}
__device__ __forceinline__ void red_add_v4(float* p, float a, float b, float c, float d) {
    asm volatile("red.global.add.v4.f32 [%0], {%1, %2, %3, %4};"
                 :: "l"(p), "f"(a), "f"(b), "f"(c), "f"(d) : "memory");
}
// split two floats into packed bf16x2 hi and lo words (elem0 in low half)
__device__ __forceinline__ void split2(float v0, float v1, uint32_t& hi, uint32_t& lo) {
    __nv_bfloat16 h0 = __float2bfloat16_rn(v0), h1 = __float2bfloat16_rn(v1);
    __nv_bfloat16 l0 = __float2bfloat16_rn(v0 - __bfloat162float(h0));
    __nv_bfloat16 l1 = __float2bfloat16_rn(v1 - __bfloat162float(h1));
    __nv_bfloat162 H = __halves2bfloat162(h0, h1);
    __nv_bfloat162 L = __halves2bfloat162(l0, l1);
    hi = *(uint32_t*)&H; lo = *(uint32_t*)&L;
}
__device__ __forceinline__ void mma_bf16(float* d, const uint32_t* a, uint32_t b0, uint32_t b1) {
    asm volatile("mma.sync.aligned.m16n8k16.row.col.f32.bf16.bf16.f32 "
        "{%0,%1,%2,%3}, {%4,%5,%6,%7}, {%8,%9}, {%0,%1,%2,%3};"
        : "+f"(d[0]), "+f"(d[1]), "+f"(d[2]), "+f"(d[3])
        : "r"(a[0]), "r"(a[1]), "r"(a[2]), "r"(a[3]), "r"(b0), "r"(b1));
}
__device__ __forceinline__ void ldsm4(uint32_t* r, uint32_t addr) {
    asm volatile("ldmatrix.sync.aligned.m8n8.x4.shared.b16 {%0,%1,%2,%3}, [%4];"
        : "=r"(r[0]), "=r"(r[1]), "=r"(r[2]), "=r"(r[3]) : "r"(addr));
}

// ---------------- prep: fold + split + fragment-order weights ----------------------
// grid (t=2, which=4), 128 threads. which: 0=Q, 1=K(fold a_rel), 2=V(fold m_rel), 3=Wa
// dynamic smem: sCol[128*128] (64KB) + sA[4096] (16KB? no: 4K floats = 16KB) -> 80KB? sA = HH*DD*DD = 4096 floats = 16KB.
__global__ void prep_weights(const float* __restrict__ Wk, const float* __restrict__ bk,
                             const float* __restrict__ Wv, const float* __restrict__ bv,
                             const float* __restrict__ Wq, const float* __restrict__ bq,
                             const float* __restrict__ Wa, const float* __restrict__ ba,
                             const float* __restrict__ a_rel, const float* __restrict__ m_rel,
                             const float* __restrict__ p_rel, int l)
{
    extern __shared__ float sm[];
    float* sCol = sm;              // [k][n] folded fp32 weight, 64KB
    float* sA   = sm + CC * CC;    // [h][d][f] 16KB

    int t = blockIdx.x, which = blockIdx.y;
    int widx = (which == 3) ? (6 + t) : (t * 3 + which);
    int n = threadIdx.x;           // output column
    size_t moff = (size_t)(l * NT + t) * CC * CC;
    size_t boff = (size_t)(l * NT + t) * CC;

    if (which == 0 || which == 3) {
        const float* W = (which == 0 ? Wq : Wa) + moff;
        const float* B = (which == 0 ? bq : ba) + boff;
        for (int k = 0; k < CC; k++) sCol[k * CC + n] = W[(size_t)k * CC + n];
        g_bias[widx][n] = B[n];
    } else {
        const float* W = (which == 1 ? Wk : Wv) + moff;
        const float* B = (which == 1 ? bk : bv) + boff;
        const float* R = (which == 1 ? a_rel : m_rel) + (size_t)(l * NT + t) * (HH * DD * DD);
        for (int i = n; i < HH * DD * DD; i += 128) {
            int h = i >> 10;
            float sc = (which == 1) ? p_rel[(l * NT + t) * HH + h] * 0.17677669529663687f : 1.0f;
            sA[i] = R[i] * sc;
        }
        __syncthreads();
        int h = n >> 5, f = n & 31;
        for (int k = 0; k < CC; k++) {
            const float* wr = W + (size_t)k * CC + h * DD;
            const float* ar = sA + h * DD * DD + f;
            float s = 0.f;
            #pragma unroll 8
            for (int d = 0; d < DD; d++) s += wr[d] * ar[d * DD];
            sCol[k * CC + n] = s;
        }
        const float* br = B + h * DD;
        const float* ar = sA + h * DD * DD + f;
        float s = 0.f;
        #pragma unroll 8
        for (int d = 0; d < DD; d++) s += br[d] * ar[d * DD];
        g_bias[widx][n] = s;
    }
    __syncthreads();

    // write fragments: lane l32 of fragment (ks,j): col = j*8 + l32/4, k0 = 16ks + (l32%4)*2
    int l32 = n & 31, quad = n >> 5;
    int g = l32 >> 2, tt = l32 & 3;
    for (int it = 0; it < 32; it++) {
        int combo = it * 4 + quad;          // 0..127
        int ks = combo >> 4, j = combo & 15;
        int col = j * 8 + g;
        int k0 = ks * 16 + tt * 2;
        uint4 frag;
        uint32_t lo0, lo1;
        split2(sCol[k0 * CC + col],       sCol[(k0 + 1) * CC + col], frag.x, lo0);
        split2(sCol[(k0 + 8) * CC + col], sCol[(k0 + 9) * CC + col], frag.y, lo1);
        frag.z = lo0; frag.w = lo1;
        g_Wf[widx][(ks * 16 + j) * 32 + l32] = frag;
    }
}

// ---------------- bf16-split mma GEMM: Y = act(X [/den]) @ W + b -------------------
// block: 128 rows x 128 cols, K=128. 256 threads = 8 warps (4 M x 2 N), warp tile 32x64.
#define OFF_WF  0                    // 64KB raw W fragments
#define OFF_XHI 65536                // 128 rows * 272B
#define OFF_XLO 100352
#define OFF_BIA 135168               // 512B
#define SMEM_TC 135680

__global__ void __launch_bounds__(256, 1)
gemm_mma(const float* __restrict__ Xbase, int mode)
{
    extern __shared__ char smem[];
    uint32_t sb = smem_u32(smem);
    int tid = threadIdx.x, wid = tid >> 5, lane = tid & 31;

    int widx; const float* X; float* Y; const float* den = nullptr;
    if (mode == 0) {
        widx = blockIdx.y;
        int t = widx / 3, which = widx % 3;
        X = Xbase + (size_t)t * NN * CC;
        Y = (which == 0) ? g_q[t] : (which == 1) ? g_k[t] : g_v[t];
    } else {
        int t = blockIdx.y; widx = 6 + t;
        X = g_agg[t]; Y = g_o[t]; den = g_den[t];
    }
    int row0 = blockIdx.x * 128;

    // 1. copy W fragments (raw) + bias
    {
        const uint4* src = g_Wf[widx];
        uint4* dst = (uint4*)(smem + OFF_WF);
        #pragma unroll
        for (int i = 0; i < 16; i++) dst[tid + i * 256] = src[tid + i * 256];
        if (tid < 128) ((float*)(smem + OFF_BIA))[tid] = g_bias[widx][tid];
    }
    // 2. load X tile, split into bf16 hi/lo padded tiles (row stride 272B = 68 u32)
    {
        uint32_t* xh = (uint32_t*)(smem + OFF_XHI);
        uint32_t* xl = (uint32_t*)(smem + OFF_XLO);
        #pragma unroll
        for (int i = 0; i < 16; i++) {
            int idx = tid + i * 256;          // 0..4095 float4s
            int m = idx >> 5, c4 = (idx & 31) * 4;
            int gm = row0 + m;
            float4 v = make_float4(0.f, 0.f, 0.f, 0.f);
            if (gm < NN) {
                v = *(const float4*)(X + (size_t)gm * CC + c4);
                if (den) {
                    float invd = 1.f / (den[(size_t)gm * HH + (c4 >> 5)] + 1e-16f);
                    v.x = gelu_tanh(v.x * invd); v.y = gelu_tanh(v.y * invd);
                    v.z = gelu_tanh(v.z * invd); v.w = gelu_tanh(v.w * invd);
                }
            }
            uint32_t h0, l0, h1, l1;
            split2(v.x, v.y, h0, l0);
            split2(v.z, v.w, h1, l1);
            int off = m * 68 + (c4 >> 1);
            *(uint2*)(xh + off) = make_uint2(h0, h1);
            *(uint2*)(xl + off) = make_uint2(l0, l1);
        }
    }
    __syncthreads();

    int warpM = (wid & 3) * 32;        // M offset of warp tile
    int jbase = (wid >> 2) * 8;        // N8-tile base index (warpN/8)

    float acc[2][8][4];
    #pragma unroll
    for (int mt = 0; mt < 2; mt++)
        #pragma unroll
        for (int nt = 0; nt < 8; nt++)
            #pragma unroll
            for (int r = 0; r < 4; r++) acc[mt][nt][r] = 0.f;

    uint32_t xrow = (uint32_t)(warpM + (lane & 15)) * 272 + (uint32_t)(lane >> 4) * 16;
    uint32_t ah_base = sb + OFF_XHI + xrow;
    uint32_t al_base = sb + OFF_XLO + xrow;
    const uint4* wf = (const uint4*)(smem + OFF_WF);

    #pragma unroll
    for (int ks = 0; ks < 8; ks++) {
        uint32_t ah[2][4], al[2][4];
        ldsm4(ah[0], ah_base + ks * 32);
        ldsm4(ah[1], ah_base + 16 * 272 + ks * 32);
        ldsm4(al[0], al_base + ks * 32);
        ldsm4(al[1], al_base + 16 * 272 + ks * 32);
        #pragma unroll
        for (int nt = 0; nt < 8; nt++) {
            uint4 b = wf[(ks * 16 + jbase + nt) * 32 + lane];
            #pragma unroll
            for (int mt = 0; mt < 2; mt++) {
                mma_bf16(acc[mt][nt], ah[mt], b.x, b.y);   // hi*hi
                mma_bf16(acc[mt][nt], al[mt], b.x, b.y);   // lo*hi
                mma_bf16(acc[mt][nt], ah[mt], b.z, b.w);   // hi*lo
            }
        }
    }

    // epilogue: bias + store
    const float* sbias = (const float*)(smem + OFF_BIA);
    int g = lane >> 2, tt = lane & 3;
    #pragma unroll
    for (int mt = 0; mt < 2; mt++) {
        int r0 = row0 + warpM + mt * 16 + g;
        #pragma unroll
        for (int nt = 0; nt < 8; nt++) {
            int c = jbase * 8 + nt * 8 + tt * 2;
            float b0 = sbias[c], b1 = sbias[c + 1];
            if (r0 < NN)
                *(float2*)(Y + (size_t)r0 * CC + c) =
                    make_float2(acc[mt][nt][0] + b0, acc[mt][nt][1] + b1);
            if (r0 + 8 < NN)
                *(float2*)(Y + (size_t)(r0 + 8) * CC + c) =
                    make_float2(acc[mt][nt][2] + b0, acc[mt][nt][3] + b1);
        }
    }
}

// ---------------- fused edge pass (unchanged) --------------------------------------
__global__ void edge_fused(const int* __restrict__ ei)
{
    int e = blockIdx.y;
    int id = blockIdx.x * 8 + (threadIdx.x >> 5);
    if (id >= EE) return;
    int lane = threadIdx.x & 31;
    int si = ei[(size_t)(e * 2 + 0) * EE + id];
    int di = ei[(size_t)(e * 2 + 1) * EE + id];
    int st = e, dt = 1 - e;

    float4 kv = ((const float4*)(g_k[st] + (size_t)si * CC))[lane];
    float4 qv = ((const float4*)(g_q[dt] + (size_t)di * CC))[lane];
    float s = kv.x * qv.x + kv.y * qv.y + kv.z * qv.z + kv.w * qv.w;
    s += __shfl_xor_sync(0xffffffffu, s, 1);
    s += __shfl_xor_sync(0xffffffffu, s, 2);
    s += __shfl_xor_sync(0xffffffffu, s, 4);
    float a = expf(s);
    if ((lane & 7) == 0)
        atomicAdd(&g_den[dt][(size_t)di * HH + (lane >> 3)], a);

    float4 vv = ((const float4*)(g_v[st] + (size_t)si * CC))[lane];
    float* dst = g_agg[dt] + (size_t)di * CC + lane * 4;
    red_add_v4(dst, a * vv.x, a * vv.y, a * vv.z, a * vv.w);
}

// ---------------- gated skip + LayerNorm + ReLU (unchanged) ------------------------
__global__ void post_ln(const float* __restrict__ o, const float* __restrict__ xin,
                        float* __restrict__ xout, float* __restrict__ dout,
                        const float* __restrict__ skip, const float* __restrict__ lng,
                        const float* __restrict__ lnb, int l)
{
    int t = blockIdx.y;
    int warp = threadIdx.x >> 5, lane = threadIdx.x & 31;
    int n = blockIdx.x * 8 + warp;
    if (n >= NN) return;
    size_t base = ((size_t)t * NN + n) * CC;

    float4 o4 = ((const float4*)(o + base))[lane];
    float4 x4 = ((const float4*)(xin + base))[lane];
    float beta = 1.f / (1.f + expf(-skip[l * NT + t]));
    float4 v;
    v.x = beta * o4.x + (1.f - beta) * x4.x;
    v.y = beta * o4.y + (1.f - beta) * x4.y;
    v.z = beta * o4.z + (1.f - beta) * x4.z;
    v.w = beta * o4.w + (1.f - beta) * x4.w;

    float s  = v.x + v.y + v.z + v.w;
    float sq = v.x * v.x + v.y * v.y + v.z * v.z + v.w * v.w;
    #pragma unroll
    for (int m = 16; m; m >>= 1) {
        s  += __shfl_xor_sync(0xffffffffu, s,  m);
        sq += __shfl_xor_sync(0xffffffffu, sq, m);
    }
    float mu  = s * (1.f / 128.f);
    float var = sq * (1.f / 128.f) - mu * mu;
    float inv = rsqrtf(var + 1e-5f);

    float4 g4 = ((const float4*)(lng + (size_t)(l * NT + t) * CC))[lane];
    float4 b4 = ((const float4*)(lnb + (size_t)(l * NT + t) * CC))[lane];
    float4 y;
    y.x = fmaxf((v.x - mu) * inv * g4.x + b4.x, 0.f);
    y.y = fmaxf((v.y - mu) * inv * g4.y + b4.y, 0.f);
    y.z = fmaxf((v.z - mu) * inv * g4.z + b4.z, 0.f);
    y.w = fmaxf((v.w - mu) * inv * g4.w + b4.w, 0.f);
    ((float4*)(xout + base))[lane] = y;
    if (dout != nullptr && t == 0)
        ((float4*)(dout + (size_t)n * CC))[lane] = y;
}

// ---------------- host orchestration ------------------------------------------------
extern "C" void kernel_launch(void* const* d_in, const int* in_sizes, int n_in,
                              void* d_out, int out_size)
{
    const float* x     = (const float*)d_in[0];
    const int*   ei    = (const int*)d_in[1];   // int32 on device (JAX x64 disabled)
    const float* Wk    = (const float*)d_in[2];
    const float* bk    = (const float*)d_in[3];
    const float* Wq    = (const float*)d_in[4];
    const float* bq    = (const float*)d_in[5];
    const float* Wv    = (const float*)d_in[6];
    const float* bv    = (const float*)d_in[7];
    const float* Wa    = (const float*)d_in[8];
    const float* ba    = (const float*)d_in[9];
    const float* skip  = (const float*)d_in[10];
    const float* a_rel = (const float*)d_in[11];
    const float* m_rel = (const float*)d_in[12];
    const float* p_rel = (const float*)d_in[13];
    const float* ln_g  = (const float*)d_in[14];
    const float* ln_b  = (const float*)d_in[15];
    float* out = (float*)d_out;

    void *pagg, *pxb, *pden, *po;
    cudaGetSymbolAddress(&pagg, g_agg);
    cudaGetSymbolAddress(&pxb,  g_xb);
    cudaGetSymbolAddress(&pden, g_den);
    cudaGetSymbolAddress(&po,   g_o);

    const int PREP_SMEM = (CC * CC + HH * DD * DD) * 4;   // 80KB
    cudaFuncSetAttribute(prep_weights, cudaFuncAttributeMaxDynamicSharedMemorySize, PREP_SMEM);
    cudaFuncSetAttribute(gemm_mma, cudaFuncAttributeMaxDynamicSharedMemorySize, SMEM_TC);

    dim3 qkv_grid(NTILES, 6);
    dim3 wa_grid(NTILES, 2);
    dim3 edge_grid(EE / 8, 2);
    dim3 ln_grid((NN + 7) / 8, 2);

    for (int l = 0; l < 2; l++) {
        const float* xin = (l == 0) ? x : (const float*)pxb;

        cudaMemsetAsync(pagg, 0, sizeof(float) * (size_t)NT * NN * CC);
        cudaMemsetAsync(pden, 0, sizeof(float) * (size_t)NT * NN * HH);

        prep_weights<<<dim3(2, 4), 128, PREP_SMEM>>>(Wk, bk, Wv, bv, Wq, bq, Wa, ba,
                                                     a_rel, m_rel, p_rel, l);

        gemm_mma<<<qkv_grid, 256, SMEM_TC>>>(xin, 0);

        edge_fused<<<edge_grid, 256>>>(ei);

        gemm_mma<<<wa_grid, 256, SMEM_TC>>>(nullptr, 1);

        post_ln<<<ln_grid, 256>>>((const float*)po, xin, (float*)pxb,
                                  (l == 1) ? out : nullptr, skip, ln_g, ln_b, l);
    }
}

// round 6
// speedup vs baseline: 1.7400x; 1.0628x over previous
#include <cuda_runtime.h>
#include <cuda_bf16.h>
#include <math.h>
#include <stdint.h>

#define NT 2
#define NN 50000
#define EE 400000
#define CC 128
#define HH 4
#define DD 32
#define NTILES 391   // ceil(50000/128)

// ---------------- device scratch (allocation-free: static globals) ----------------
__device__ float g_q  [NT][(size_t)NN*CC];
__device__ float g_k  [NT][(size_t)NN*CC];
__device__ float g_v  [NT][(size_t)NN*CC];
__device__ float g_agg[NT][(size_t)NN*CC];   // UNNORMALIZED sum of a*v
__device__ float g_o  [NT][(size_t)NN*CC];
__device__ float g_xb [NT][(size_t)NN*CC];
__device__ float g_den[NT][(size_t)NN*HH];
// W in mma B-fragment order: [inst][ (ks*16+j)*32+lane ] = {hi_b0,hi_b1,lo_b0,lo_b1}
// inst: t*3+{Q,K,V} for t=0,1 ; 6+t for Wa
__device__ uint4 g_Wf  [8][4096];
__device__ float g_bias[8][CC];

// ---------------- small helpers ----------------------------------------------------
__device__ __forceinline__ uint32_t smem_u32(const void* p) {
    uint32_t a;
    asm("{ .reg .u64 t; cvta.to.shared.u64 t, %1; cvt.u32.u64 %0, t; }" : "=r"(a) : "l"(p));
    return a;
}
__device__ __forceinline__ float gelu_tanh(float v) {
    const float c = 0.7978845608028654f;
    float t = tanhf(c * (v + 0.044715f * v * v * v));
    return 0.5f * v * (1.0f + t);
}
__device__ __forceinline__ void red_add_v4(float* p, float a, float b, float c, float d) {
    asm volatile("red.global.add.v4.f32 [%0], {%1, %2, %3, %4};"
                 :: "l"(p), "f"(a), "f"(b), "f"(c), "f"(d) : "memory");
}
// split two floats into packed bf16x2 hi and lo words (elem0 in low half)
__device__ __forceinline__ void split2(float v0, float v1, uint32_t& hi, uint32_t& lo) {
    __nv_bfloat16 h0 = __float2bfloat16_rn(v0), h1 = __float2bfloat16_rn(v1);
    __nv_bfloat16 l0 = __float2bfloat16_rn(v0 - __bfloat162float(h0));
    __nv_bfloat16 l1 = __float2bfloat16_rn(v1 - __bfloat162float(h1));
    __nv_bfloat162 H = __halves2bfloat162(h0, h1);
    __nv_bfloat162 L = __halves2bfloat162(l0, l1);
    hi = *(uint32_t*)&H; lo = *(uint32_t*)&L;
}
__device__ __forceinline__ void mma_bf16(float* d, const uint32_t* a, uint32_t b0, uint32_t b1) {
    asm volatile("mma.sync.aligned.m16n8k16.row.col.f32.bf16.bf16.f32 "
        "{%0,%1,%2,%3}, {%4,%5,%6,%7}, {%8,%9}, {%0,%1,%2,%3};"
        : "+f"(d[0]), "+f"(d[1]), "+f"(d[2]), "+f"(d[3])
        : "r"(a[0]), "r"(a[1]), "r"(a[2]), "r"(a[3]), "r"(b0), "r"(b1));
}
__device__ __forceinline__ void ldsm4(uint32_t* r, uint32_t addr) {
    asm volatile("ldmatrix.sync.aligned.m8n8.x4.shared.b16 {%0,%1,%2,%3}, [%4];"
        : "=r"(r[0]), "=r"(r[1]), "=r"(r[2]), "=r"(r[3]) : "r"(addr));
}

// ---------------- prep: fold + split + fragment-order weights ----------------------
// grid (t=2, which=4), 128 threads. which: 0=Q, 1=K(fold a_rel), 2=V(fold m_rel), 3=Wa
__global__ void prep_weights(const float* __restrict__ Wk, const float* __restrict__ bk,
                             const float* __restrict__ Wv, const float* __restrict__ bv,
                             const float* __restrict__ Wq, const float* __restrict__ bq,
                             const float* __restrict__ Wa, const float* __restrict__ ba,
                             const float* __restrict__ a_rel, const float* __restrict__ m_rel,
                             const float* __restrict__ p_rel, int l)
{
    extern __shared__ float sm[];
    float* sCol = sm;              // [k][n] folded fp32 weight, 64KB
    float* sA   = sm + CC * CC;    // [h][d][f] 16KB

    int t = blockIdx.x, which = blockIdx.y;
    int widx = (which == 3) ? (6 + t) : (t * 3 + which);
    int n = threadIdx.x;           // output column
    size_t moff = (size_t)(l * NT + t) * CC * CC;
    size_t boff = (size_t)(l * NT + t) * CC;

    if (which == 0 || which == 3) {
        const float* W = (which == 0 ? Wq : Wa) + moff;
        const float* B = (which == 0 ? bq : ba) + boff;
        for (int k = 0; k < CC; k++) sCol[k * CC + n] = W[(size_t)k * CC + n];
        g_bias[widx][n] = B[n];
    } else {
        const float* W = (which == 1 ? Wk : Wv) + moff;
        const float* B = (which == 1 ? bk : bv) + boff;
        const float* R = (which == 1 ? a_rel : m_rel) + (size_t)(l * NT + t) * (HH * DD * DD);
        for (int i = n; i < HH * DD * DD; i += 128) {
            int h = i >> 10;
            float sc = (which == 1) ? p_rel[(l * NT + t) * HH + h] * 0.17677669529663687f : 1.0f;
            sA[i] = R[i] * sc;
        }
        __syncthreads();
        int h = n >> 5, f = n & 31;
        for (int k = 0; k < CC; k++) {
            const float* wr = W + (size_t)k * CC + h * DD;
            const float* ar = sA + h * DD * DD + f;
            float s = 0.f;
            #pragma unroll 8
            for (int d = 0; d < DD; d++) s += wr[d] * ar[d * DD];
            sCol[k * CC + n] = s;
        }
        const float* br = B + h * DD;
        const float* ar = sA + h * DD * DD + f;
        float s = 0.f;
        #pragma unroll 8
        for (int d = 0; d < DD; d++) s += br[d] * ar[d * DD];
        g_bias[widx][n] = s;
    }
    __syncthreads();

    // write fragments: lane l32 of fragment (ks,j): col = j*8 + l32/4, k0 = 16ks + (l32%4)*2
    int l32 = n & 31, quad = n >> 5;
    int g = l32 >> 2, tt = l32 & 3;
    for (int it = 0; it < 32; it++) {
        int combo = it * 4 + quad;          // 0..127
        int ks = combo >> 4, j = combo & 15;
        int col = j * 8 + g;
        int k0 = ks * 16 + tt * 2;
        uint4 frag;
        uint32_t lo0, lo1;
        split2(sCol[k0 * CC + col],       sCol[(k0 + 1) * CC + col], frag.x, lo0);
        split2(sCol[(k0 + 8) * CC + col], sCol[(k0 + 9) * CC + col], frag.y, lo1);
        frag.z = lo0; frag.w = lo1;
        g_Wf[widx][(ks * 16 + j) * 32 + l32] = frag;
    }
}

// ---------------- bf16-split mma GEMM: Y = act(X [/den]) @ W + b -------------------
// block: 128 rows x 128 cols, K=128. 512 threads = 16 warps (4 M x 4 N), warp tile 32x32.
#define OFF_WF  0                    // 64KB raw W fragments
#define OFF_XHI 65536                // 128 rows * 272B
#define OFF_XLO 100352
#define OFF_BIA 135168               // 512B
#define SMEM_TC 135680

__global__ void __launch_bounds__(512, 1)
gemm_mma(const float* __restrict__ Xbase, int mode)
{
    extern __shared__ char smem[];
    uint32_t sb = smem_u32(smem);
    int tid = threadIdx.x, wid = tid >> 5, lane = tid & 31;

    int widx; const float* X; float* Y; const float* den = nullptr;
    if (mode == 0) {
        widx = blockIdx.y;
        int t = widx / 3, which = widx % 3;
        X = Xbase + (size_t)t * NN * CC;
        Y = (which == 0) ? g_q[t] : (which == 1) ? g_k[t] : g_v[t];
    } else {
        int t = blockIdx.y; widx = 6 + t;
        X = g_agg[t]; Y = g_o[t]; den = g_den[t];
    }
    int row0 = blockIdx.x * 128;

    // 1. copy W fragments (raw) + bias
    {
        const uint4* src = g_Wf[widx];
        uint4* dst = (uint4*)(smem + OFF_WF);
        #pragma unroll
        for (int i = 0; i < 8; i++) dst[tid + i * 512] = src[tid + i * 512];
        if (tid < 128) ((float*)(smem + OFF_BIA))[tid] = g_bias[widx][tid];
    }
    // 2. load X tile, split into bf16 hi/lo padded tiles (row stride 272B = 68 u32)
    {
        uint32_t* xh = (uint32_t*)(smem + OFF_XHI);
        uint32_t* xl = (uint32_t*)(smem + OFF_XLO);
        #pragma unroll
        for (int i = 0; i < 8; i++) {
            int idx = tid + i * 512;          // 0..4095 float4s
            int m = idx >> 5, c4 = (idx & 31) * 4;
            int gm = row0 + m;
            float4 v = make_float4(0.f, 0.f, 0.f, 0.f);
            if (gm < NN) {
                v = *(const float4*)(X + (size_t)gm * CC + c4);
                if (den) {
                    float invd = 1.f / (den[(size_t)gm * HH + (c4 >> 5)] + 1e-16f);
                    v.x = gelu_tanh(v.x * invd); v.y = gelu_tanh(v.y * invd);
                    v.z = gelu_tanh(v.z * invd); v.w = gelu_tanh(v.w * invd);
                }
            }
            uint32_t h0, l0, h1, l1;
            split2(v.x, v.y, h0, l0);
            split2(v.z, v.w, h1, l1);
            int off = m * 68 + (c4 >> 1);
            *(uint2*)(xh + off) = make_uint2(h0, h1);
            *(uint2*)(xl + off) = make_uint2(l0, l1);
        }
    }
    __syncthreads();

    int warpM = (wid & 3) * 32;        // M offset of warp tile
    int jbase = (wid >> 2) * 4;        // N8-tile base index (j = jbase..jbase+3)

    float acc[2][4][4];
    #pragma unroll
    for (int mt = 0; mt < 2; mt++)
        #pragma unroll
        for (int nt = 0; nt < 4; nt++)
            #pragma unroll
            for (int r = 0; r < 4; r++) acc[mt][nt][r] = 0.f;

    uint32_t xrow = (uint32_t)(warpM + (lane & 15)) * 272 + (uint32_t)(lane >> 4) * 16;
    uint32_t ah_base = sb + OFF_XHI + xrow;
    uint32_t al_base = sb + OFF_XLO + xrow;
    const uint4* wf = (const uint4*)(smem + OFF_WF);

    #pragma unroll
    for (int ks = 0; ks < 8; ks++) {
        uint32_t ah[2][4], al[2][4];
        ldsm4(ah[0], ah_base + ks * 32);
        ldsm4(ah[1], ah_base + 16 * 272 + ks * 32);
        ldsm4(al[0], al_base + ks * 32);
        ldsm4(al[1], al_base + 16 * 272 + ks * 32);
        #pragma unroll
        for (int nt = 0; nt < 4; nt++) {
            uint4 b = wf[(ks * 16 + jbase + nt) * 32 + lane];
            #pragma unroll
            for (int mt = 0; mt < 2; mt++) {
                mma_bf16(acc[mt][nt], ah[mt], b.x, b.y);   // hi*hi
                mma_bf16(acc[mt][nt], al[mt], b.x, b.y);   // lo*hi
                mma_bf16(acc[mt][nt], ah[mt], b.z, b.w);   // hi*lo
            }
        }
    }

    // epilogue: bias + store
    const float* sbias = (const float*)(smem + OFF_BIA);
    int g = lane >> 2, tt = lane & 3;
    #pragma unroll
    for (int mt = 0; mt < 2; mt++) {
        int r0 = row0 + warpM + mt * 16 + g;
        #pragma unroll
        for (int nt = 0; nt < 4; nt++) {
            int c = (jbase + nt) * 8 + tt * 2;
            float b0 = sbias[c], b1 = sbias[c + 1];
            if (r0 < NN)
                *(float2*)(Y + (size_t)r0 * CC + c) =
                    make_float2(acc[mt][nt][0] + b0, acc[mt][nt][1] + b1);
            if (r0 + 8 < NN)
                *(float2*)(Y + (size_t)(r0 + 8) * CC + c) =
                    make_float2(acc[mt][nt][2] + b0, acc[mt][nt][3] + b1);
        }
    }
}

// ---------------- fused edge pass (unchanged) --------------------------------------
__global__ void edge_fused(const int* __restrict__ ei)
{
    int e = blockIdx.y;
    int id = blockIdx.x * 8 + (threadIdx.x >> 5);
    if (id >= EE) return;
    int lane = threadIdx.x & 31;
    int si = ei[(size_t)(e * 2 + 0) * EE + id];
    int di = ei[(size_t)(e * 2 + 1) * EE + id];
    int st = e, dt = 1 - e;

    float4 kv = ((const float4*)(g_k[st] + (size_t)si * CC))[lane];
    float4 qv = ((const float4*)(g_q[dt] + (size_t)di * CC))[lane];
    float s = kv.x * qv.x + kv.y * qv.y + kv.z * qv.z + kv.w * qv.w;
    s += __shfl_xor_sync(0xffffffffu, s, 1);
    s += __shfl_xor_sync(0xffffffffu, s, 2);
    s += __shfl_xor_sync(0xffffffffu, s, 4);
    float a = expf(s);
    if ((lane & 7) == 0)
        atomicAdd(&g_den[dt][(size_t)di * HH + (lane >> 3)], a);

    float4 vv = ((const float4*)(g_v[st] + (size_t)si * CC))[lane];
    float* dst = g_agg[dt] + (size_t)di * CC + lane * 4;
    red_add_v4(dst, a * vv.x, a * vv.y, a * vv.z, a * vv.w);
}

// ---------------- gated skip + LayerNorm + ReLU (unchanged) ------------------------
__global__ void post_ln(const float* __restrict__ o, const float* __restrict__ xin,
                        float* __restrict__ xout, float* __restrict__ dout,
                        const float* __restrict__ skip, const float* __restrict__ lng,
                        const float* __restrict__ lnb, int l)
{
    int t = blockIdx.y;
    int warp = threadIdx.x >> 5, lane = threadIdx.x & 31;
    int n = blockIdx.x * 8 + warp;
    if (n >= NN) return;
    size_t base = ((size_t)t * NN + n) * CC;

    float4 o4 = ((const float4*)(o + base))[lane];
    float4 x4 = ((const float4*)(xin + base))[lane];
    float beta = 1.f / (1.f + expf(-skip[l * NT + t]));
    float4 v;
    v.x = beta * o4.x + (1.f - beta) * x4.x;
    v.y = beta * o4.y + (1.f - beta) * x4.y;
    v.z = beta * o4.z + (1.f - beta) * x4.z;
    v.w = beta * o4.w + (1.f - beta) * x4.w;

    float s  = v.x + v.y + v.z + v.w;
    float sq = v.x * v.x + v.y * v.y + v.z * v.z + v.w * v.w;
    #pragma unroll
    for (int m = 16; m; m >>= 1) {
        s  += __shfl_xor_sync(0xffffffffu, s,  m);
        sq += __shfl_xor_sync(0xffffffffu, sq, m);
    }
    float mu  = s * (1.f / 128.f);
    float var = sq * (1.f / 128.f) - mu * mu;
    float inv = rsqrtf(var + 1e-5f);

    float4 g4 = ((const float4*)(lng + (size_t)(l * NT + t) * CC))[lane];
    float4 b4 = ((const float4*)(lnb + (size_t)(l * NT + t) * CC))[lane];
    float4 y;
    y.x = fmaxf((v.x - mu) * inv * g4.x + b4.x, 0.f);
    y.y = fmaxf((v.y - mu) * inv * g4.y + b4.y, 0.f);
    y.z = fmaxf((v.z - mu) * inv * g4.z + b4.z, 0.f);
    y.w = fmaxf((v.w - mu) * inv * g4.w + b4.w, 0.f);
    ((float4*)(xout + base))[lane] = y;
    if (dout != nullptr && t == 0)
        ((float4*)(dout + (size_t)n * CC))[lane] = y;
}

// ---------------- host orchestration ------------------------------------------------
extern "C" void kernel_launch(void* const* d_in, const int* in_sizes, int n_in,
                              void* d_out, int out_size)
{
    const float* x     = (const float*)d_in[0];
    const int*   ei    = (const int*)d_in[1];   // int32 on device (JAX x64 disabled)
    const float* Wk    = (const float*)d_in[2];
    const float* bk    = (const float*)d_in[3];
    const float* Wq    = (const float*)d_in[4];
    const float* bq    = (const float*)d_in[5];
    const float* Wv    = (const float*)d_in[6];
    const float* bv    = (const float*)d_in[7];
    const float* Wa    = (const float*)d_in[8];
    const float* ba    = (const float*)d_in[9];
    const float* skip  = (const float*)d_in[10];
    const float* a_rel = (const float*)d_in[11];
    const float* m_rel = (const float*)d_in[12];
    const float* p_rel = (const float*)d_in[13];
    const float* ln_g  = (const float*)d_in[14];
    const float* ln_b  = (const float*)d_in[15];
    float* out = (float*)d_out;

    void *pagg, *pxb, *pden, *po;
    cudaGetSymbolAddress(&pagg, g_agg);
    cudaGetSymbolAddress(&pxb,  g_xb);
    cudaGetSymbolAddress(&pden, g_den);
    cudaGetSymbolAddress(&po,   g_o);

    const int PREP_SMEM = (CC * CC + HH * DD * DD) * 4;   // 80KB
    cudaFuncSetAttribute(prep_weights, cudaFuncAttributeMaxDynamicSharedMemorySize, PREP_SMEM);
    cudaFuncSetAttribute(gemm_mma, cudaFuncAttributeMaxDynamicSharedMemorySize, SMEM_TC);

    dim3 qkv_grid(NTILES, 6);
    dim3 wa_grid(NTILES, 2);
    dim3 edge_grid(EE / 8, 2);
    dim3 ln_grid((NN + 7) / 8, 2);

    for (int l = 0; l < 2; l++) {
        const float* xin = (l == 0) ? x : (const float*)pxb;

        cudaMemsetAsync(pagg, 0, sizeof(float) * (size_t)NT * NN * CC);
        cudaMemsetAsync(pden, 0, sizeof(float) * (size_t)NT * NN * HH);

        prep_weights<<<dim3(2, 4), 128, PREP_SMEM>>>(Wk, bk, Wv, bv, Wq, bq, Wa, ba,
                                                     a_rel, m_rel, p_rel, l);

        gemm_mma<<<qkv_grid, 512, SMEM_TC>>>(xin, 0);

        edge_fused<<<edge_grid, 256>>>(ei);

        gemm_mma<<<wa_grid, 512, SMEM_TC>>>(nullptr, 1);

        post_ln<<<ln_grid, 256>>>((const float*)po, xin, (float*)pxb,
                                  (l == 1) ? out : nullptr, skip, ln_g, ln_b, l);
    }
}

// round 7
// speedup vs baseline: 1.8145x; 1.0428x over previous
#include <cuda_runtime.h>
#include <cuda_bf16.h>
#include <math.h>
#include <stdint.h>

#define NT 2
#define NN 50000
#define EE 400000
#define CC 128
#define HH 4
#define DD 32
#define NTILES64 782   // ceil(50000/64)

// ---------------- device scratch (allocation-free: static globals) ----------------
__device__ float g_q  [NT][(size_t)NN*CC];
__device__ float g_k  [NT][(size_t)NN*CC];
__device__ float g_v  [NT][(size_t)NN*CC];
__device__ float g_agg[NT][(size_t)NN*CC];   // UNNORMALIZED sum of a*v
__device__ float g_o  [NT][(size_t)NN*CC];
__device__ float g_xb [NT][(size_t)NN*CC];
__device__ float g_den[NT][(size_t)NN*HH];
// W in mma B-fragment order: [inst][ (ks*16+j)*32+lane ] = {hi_b0,hi_b1,lo_b0,lo_b1}
// inst: t*3+{Q,K,V} for t=0,1 ; 6+t for Wa
__device__ uint4 g_Wf  [8][4096];
__device__ float g_bias[8][CC];

// ---------------- small helpers ----------------------------------------------------
__device__ __forceinline__ uint32_t smem_u32(const void* p) {
    uint32_t a;
    asm("{ .reg .u64 t; cvta.to.shared.u64 t, %1; cvt.u32.u64 %0, t; }" : "=r"(a) : "l"(p));
    return a;
}
// gelu(tanh approx) == v * sigmoid(2c(v + 0.044715 v^3)) — exact identity, MUFU-cheap
__device__ __forceinline__ float gelu_fast(float v) {
    float z = 1.5957691216057308f * (v + 0.044715f * v * v * v);
    return __fdividef(v, 1.0f + __expf(-z));
}
__device__ __forceinline__ void red_add_v4(float* p, float a, float b, float c, float d) {
    asm volatile("red.global.add.v4.f32 [%0], {%1, %2, %3, %4};"
                 :: "l"(p), "f"(a), "f"(b), "f"(c), "f"(d) : "memory");
}
// split two floats into packed bf16x2 hi and lo words (elem0 in low half)
__device__ __forceinline__ void split2(float v0, float v1, uint32_t& hi, uint32_t& lo) {
    __nv_bfloat16 h0 = __float2bfloat16_rn(v0), h1 = __float2bfloat16_rn(v1);
    __nv_bfloat16 l0 = __float2bfloat16_rn(v0 - __bfloat162float(h0));
    __nv_bfloat16 l1 = __float2bfloat16_rn(v1 - __bfloat162float(h1));
    __nv_bfloat162 H = __halves2bfloat162(h0, h1);
    __nv_bfloat162 L = __halves2bfloat162(l0, l1);
    hi = *(uint32_t*)&H; lo = *(uint32_t*)&L;
}
__device__ __forceinline__ void mma_bf16(float* d, const uint32_t* a, uint32_t b0, uint32_t b1) {
    asm volatile("mma.sync.aligned.m16n8k16.row.col.f32.bf16.bf16.f32 "
        "{%0,%1,%2,%3}, {%4,%5,%6,%7}, {%8,%9}, {%0,%1,%2,%3};"
        : "+f"(d[0]), "+f"(d[1]), "+f"(d[2]), "+f"(d[3])
        : "r"(a[0]), "r"(a[1]), "r"(a[2]), "r"(a[3]), "r"(b0), "r"(b1));
}
__device__ __forceinline__ void ldsm4(uint32_t* r, uint32_t addr) {
    asm volatile("ldmatrix.sync.aligned.m8n8.x4.shared.b16 {%0,%1,%2,%3}, [%4];"
        : "=r"(r[0]), "=r"(r[1]), "=r"(r[2]), "=r"(r[3]) : "r"(addr));
}

// ---------------- prep: fold + split + fragment-order weights ----------------------
// grid (t=2, which=4), 128 threads. which: 0=Q, 1=K(fold a_rel), 2=V(fold m_rel), 3=Wa
__global__ void prep_weights(const float* __restrict__ Wk, const float* __restrict__ bk,
                             const float* __restrict__ Wv, const float* __restrict__ bv,
                             const float* __restrict__ Wq, const float* __restrict__ bq,
                             const float* __restrict__ Wa, const float* __restrict__ ba,
                             const float* __restrict__ a_rel, const float* __restrict__ m_rel,
                             const float* __restrict__ p_rel, int l)
{
    extern __shared__ float sm[];
    float* sCol = sm;              // [k][n] folded fp32 weight, 64KB
    float* sA   = sm + CC * CC;    // [h][d][f] 16KB

    int t = blockIdx.x, which = blockIdx.y;
    int widx = (which == 3) ? (6 + t) : (t * 3 + which);
    int n = threadIdx.x;           // output column
    size_t moff = (size_t)(l * NT + t) * CC * CC;
    size_t boff = (size_t)(l * NT + t) * CC;

    if (which == 0 || which == 3) {
        const float* W = (which == 0 ? Wq : Wa) + moff;
        const float* B = (which == 0 ? bq : ba) + boff;
        for (int k = 0; k < CC; k++) sCol[k * CC + n] = W[(size_t)k * CC + n];
        g_bias[widx][n] = B[n];
    } else {
        const float* W = (which == 1 ? Wk : Wv) + moff;
        const float* B = (which == 1 ? bk : bv) + boff;
        const float* R = (which == 1 ? a_rel : m_rel) + (size_t)(l * NT + t) * (HH * DD * DD);
        for (int i = n; i < HH * DD * DD; i += 128) {
            int h = i >> 10;
            float sc = (which == 1) ? p_rel[(l * NT + t) * HH + h] * 0.17677669529663687f : 1.0f;
            sA[i] = R[i] * sc;
        }
        __syncthreads();
        int h = n >> 5, f = n & 31;
        for (int k = 0; k < CC; k++) {
            const float* wr = W + (size_t)k * CC + h * DD;
            const float* ar = sA + h * DD * DD + f;
            float s = 0.f;
            #pragma unroll 8
            for (int d = 0; d < DD; d++) s += wr[d] * ar[d * DD];
            sCol[k * CC + n] = s;
        }
        const float* br = B + h * DD;
        const float* ar = sA + h * DD * DD + f;
        float s = 0.f;
        #pragma unroll 8
        for (int d = 0; d < DD; d++) s += br[d] * ar[d * DD];
        g_bias[widx][n] = s;
    }
    __syncthreads();

    // write fragments: lane l32 of fragment (ks,j): col = j*8 + l32/4, k0 = 16ks + (l32%4)*2
    int l32 = n & 31, quad = n >> 5;
    int g = l32 >> 2, tt = l32 & 3;
    for (int it = 0; it < 32; it++) {
        int combo = it * 4 + quad;          // 0..127
        int ks = combo >> 4, j = combo & 15;
        int col = j * 8 + g;
        int k0 = ks * 16 + tt * 2;
        uint4 frag;
        uint32_t lo0, lo1;
        split2(sCol[k0 * CC + col],       sCol[(k0 + 1) * CC + col], frag.x, lo0);
        split2(sCol[(k0 + 8) * CC + col], sCol[(k0 + 9) * CC + col], frag.y, lo1);
        frag.z = lo0; frag.w = lo1;
        g_Wf[widx][(ks * 16 + j) * 32 + l32] = frag;
    }
}

// ---------------- bf16-split mma GEMM: Y = act(X [/den]) @ W + b -------------------
// block: 64 rows x 128 cols, K=128. 256 threads = 8 warps (4 M x 2 N), warp tile 16x64.
// W fragments read directly from gmem (L1-resident); only X hi/lo in smem (35KB -> 3 CTA/SM).
#define OFF_XHI 0                    // 64 rows * 272B
#define OFF_XLO 17408
#define SMEM_TC 34816

__global__ void __launch_bounds__(256, 3)
gemm_mma(const float* __restrict__ Xbase, int mode)
{
    extern __shared__ char smem[];
    uint32_t sb = smem_u32(smem);
    int tid = threadIdx.x, wid = tid >> 5, lane = tid & 31;

    int widx; const float* X; float* Y; const float* den = nullptr;
    if (mode == 0) {
        widx = blockIdx.y;
        int t = widx / 3, which = widx % 3;
        X = Xbase + (size_t)t * NN * CC;
        Y = (which == 0) ? g_q[t] : (which == 1) ? g_k[t] : g_v[t];
    } else {
        int t = blockIdx.y; widx = 6 + t;
        X = g_agg[t]; Y = g_o[t]; den = g_den[t];
    }
    int row0 = blockIdx.x * 64;
    const uint4* __restrict__ wf = g_Wf[widx];
    const float* __restrict__ bias = g_bias[widx];

    // load X tile (64 rows), split into bf16 hi/lo padded tiles (row stride 272B)
    {
        uint32_t* xh = (uint32_t*)(smem + OFF_XHI);
        uint32_t* xl = (uint32_t*)(smem + OFF_XLO);
        #pragma unroll
        for (int i = 0; i < 8; i++) {
            int idx = tid + i * 256;          // 0..2047 float4s
            int m = idx >> 5, c4 = (idx & 31) * 4;
            int gm = row0 + m;
            float4 v = make_float4(0.f, 0.f, 0.f, 0.f);
            if (gm < NN) {
                v = *(const float4*)(X + (size_t)gm * CC + c4);
                if (den) {
                    float invd = __fdividef(1.f, den[(size_t)gm * HH + (c4 >> 5)] + 1e-16f);
                    v.x = gelu_fast(v.x * invd); v.y = gelu_fast(v.y * invd);
                    v.z = gelu_fast(v.z * invd); v.w = gelu_fast(v.w * invd);
                }
            }
            uint32_t h0, l0, h1, l1;
            split2(v.x, v.y, h0, l0);
            split2(v.z, v.w, h1, l1);
            int off = m * 68 + (c4 >> 1);
            *(uint2*)(xh + off) = make_uint2(h0, h1);
            *(uint2*)(xl + off) = make_uint2(l0, l1);
        }
    }
    __syncthreads();

    int warpM = (wid & 3) * 16;        // M offset of warp tile (16 rows)
    int jbase = (wid >> 2) * 8;        // N8-tile base (8 tiles = 64 cols)

    float acc[8][4];
    #pragma unroll
    for (int nt = 0; nt < 8; nt++)
        #pragma unroll
        for (int r = 0; r < 4; r++) acc[nt][r] = 0.f;

    uint32_t xrow = (uint32_t)(warpM + (lane & 15)) * 272 + (uint32_t)(lane >> 4) * 16;
    uint32_t ah_base = sb + OFF_XHI + xrow;
    uint32_t al_base = sb + OFF_XLO + xrow;

    #pragma unroll
    for (int ks = 0; ks < 8; ks++) {
        uint32_t ah[4], al[4];
        ldsm4(ah, ah_base + ks * 32);
        ldsm4(al, al_base + ks * 32);
        #pragma unroll
        for (int nt = 0; nt < 8; nt++) {
            uint4 b = __ldg(&wf[(ks * 16 + jbase + nt) * 32 + lane]);
            mma_bf16(acc[nt], ah, b.x, b.y);   // hi*hi
            mma_bf16(acc[nt], al, b.x, b.y);   // lo*hi
            mma_bf16(acc[nt], ah, b.z, b.w);   // hi*lo
        }
    }

    // epilogue: bias + store
    int g = lane >> 2, tt = lane & 3;
    int r0 = row0 + warpM + g;
    #pragma unroll
    for (int nt = 0; nt < 8; nt++) {
        int c = (jbase + nt) * 8 + tt * 2;
        float b0 = __ldg(&bias[c]), b1 = __ldg(&bias[c + 1]);
        if (r0 < NN)
            *(float2*)(Y + (size_t)r0 * CC + c) =
                make_float2(acc[nt][0] + b0, acc[nt][1] + b1);
        if (r0 + 8 < NN)
            *(float2*)(Y + (size_t)(r0 + 8) * CC + c) =
                make_float2(acc[nt][2] + b0, acc[nt][3] + b1);
    }
}

// ---------------- fused edge pass (unchanged) --------------------------------------
__global__ void edge_fused(const int* __restrict__ ei)
{
    int e = blockIdx.y;
    int id = blockIdx.x * 8 + (threadIdx.x >> 5);
    if (id >= EE) return;
    int lane = threadIdx.x & 31;
    int si = ei[(size_t)(e * 2 + 0) * EE + id];
    int di = ei[(size_t)(e * 2 + 1) * EE + id];
    int st = e, dt = 1 - e;

    float4 kv = ((const float4*)(g_k[st] + (size_t)si * CC))[lane];
    float4 qv = ((const float4*)(g_q[dt] + (size_t)di * CC))[lane];
    float s = kv.x * qv.x + kv.y * qv.y + kv.z * qv.z + kv.w * qv.w;
    s += __shfl_xor_sync(0xffffffffu, s, 1);
    s += __shfl_xor_sync(0xffffffffu, s, 2);
    s += __shfl_xor_sync(0xffffffffu, s, 4);
    float a = expf(s);
    if ((lane & 7) == 0)
        atomicAdd(&g_den[dt][(size_t)di * HH + (lane >> 3)], a);

    float4 vv = ((const float4*)(g_v[st] + (size_t)si * CC))[lane];
    float* dst = g_agg[dt] + (size_t)di * CC + lane * 4;
    red_add_v4(dst, a * vv.x, a * vv.y, a * vv.z, a * vv.w);
}

// ---------------- gated skip + LayerNorm + ReLU (unchanged) ------------------------
__global__ void post_ln(const float* __restrict__ o, const float* __restrict__ xin,
                        float* __restrict__ xout, float* __restrict__ dout,
                        const float* __restrict__ skip, const float* __restrict__ lng,
                        const float* __restrict__ lnb, int l)
{
    int t = blockIdx.y;
    int warp = threadIdx.x >> 5, lane = threadIdx.x & 31;
    int n = blockIdx.x * 8 + warp;
    if (n >= NN) return;
    size_t base = ((size_t)t * NN + n) * CC;

    float4 o4 = ((const float4*)(o + base))[lane];
    float4 x4 = ((const float4*)(xin + base))[lane];
    float beta = 1.f / (1.f + expf(-skip[l * NT + t]));
    float4 v;
    v.x = beta * o4.x + (1.f - beta) * x4.x;
    v.y = beta * o4.y + (1.f - beta) * x4.y;
    v.z = beta * o4.z + (1.f - beta) * x4.z;
    v.w = beta * o4.w + (1.f - beta) * x4.w;

    float s  = v.x + v.y + v.z + v.w;
    float sq = v.x * v.x + v.y * v.y + v.z * v.z + v.w * v.w;
    #pragma unroll
    for (int m = 16; m; m >>= 1) {
        s  += __shfl_xor_sync(0xffffffffu, s,  m);
        sq += __shfl_xor_sync(0xffffffffu, sq, m);
    }
    float mu  = s * (1.f / 128.f);
    float var = sq * (1.f / 128.f) - mu * mu;
    float inv = rsqrtf(var + 1e-5f);

    float4 g4 = ((const float4*)(lng + (size_t)(l * NT + t) * CC))[lane];
    float4 b4 = ((const float4*)(lnb + (size_t)(l * NT + t) * CC))[lane];
    float4 y;
    y.x = fmaxf((v.x - mu) * inv * g4.x + b4.x, 0.f);
    y.y = fmaxf((v.y - mu) * inv * g4.y + b4.y, 0.f);
    y.z = fmaxf((v.z - mu) * inv * g4.z + b4.z, 0.f);
    y.w = fmaxf((v.w - mu) * inv * g4.w + b4.w, 0.f);
    ((float4*)(xout + base))[lane] = y;
    if (dout != nullptr && t == 0)
        ((float4*)(dout + (size_t)n * CC))[lane] = y;
}

// ---------------- host orchestration ------------------------------------------------
extern "C" void kernel_launch(void* const* d_in, const int* in_sizes, int n_in,
                              void* d_out, int out_size)
{
    const float* x     = (const float*)d_in[0];
    const int*   ei    = (const int*)d_in[1];   // int32 on device (JAX x64 disabled)
    const float* Wk    = (const float*)d_in[2];
    const float* bk    = (const float*)d_in[3];
    const float* Wq    = (const float*)d_in[4];
    const float* bq    = (const float*)d_in[5];
    const float* Wv    = (const float*)d_in[6];
    const float* bv    = (const float*)d_in[7];
    const float* Wa    = (const float*)d_in[8];
    const float* ba    = (const float*)d_in[9];
    const float* skip  = (const float*)d_in[10];
    const float* a_rel = (const float*)d_in[11];
    const float* m_rel = (const float*)d_in[12];
    const float* p_rel = (const float*)d_in[13];
    const float* ln_g  = (const float*)d_in[14];
    const float* ln_b  = (const float*)d_in[15];
    float* out = (float*)d_out;

    void *pagg, *pxb, *pden, *po;
    cudaGetSymbolAddress(&pagg, g_agg);
    cudaGetSymbolAddress(&pxb,  g_xb);
    cudaGetSymbolAddress(&pden, g_den);
    cudaGetSymbolAddress(&po,   g_o);

    const int PREP_SMEM = (CC * CC + HH * DD * DD) * 4;   // 80KB
    cudaFuncSetAttribute(prep_weights, cudaFuncAttributeMaxDynamicSharedMemorySize, PREP_SMEM);
    cudaFuncSetAttribute(gemm_mma, cudaFuncAttributeMaxDynamicSharedMemorySize, SMEM_TC);

    dim3 qkv_grid(NTILES64, 6);
    dim3 wa_grid(NTILES64, 2);
    dim3 edge_grid(EE / 8, 2);
    dim3 ln_grid((NN + 7) / 8, 2);

    for (int l = 0; l < 2; l++) {
        const float* xin = (l == 0) ? x : (const float*)pxb;

        cudaMemsetAsync(pagg, 0, sizeof(float) * (size_t)NT * NN * CC);
        cudaMemsetAsync(pden, 0, sizeof(float) * (size_t)NT * NN * HH);

        prep_weights<<<dim3(2, 4), 128, PREP_SMEM>>>(Wk, bk, Wv, bv, Wq, bq, Wa, ba,
                                                     a_rel, m_rel, p_rel, l);

        gemm_mma<<<qkv_grid, 256, SMEM_TC>>>(xin, 0);

        edge_fused<<<edge_grid, 256>>>(ei);

        gemm_mma<<<wa_grid, 256, SMEM_TC>>>(nullptr, 1);

        post_ln<<<ln_grid, 256>>>((const float*)po, xin, (float*)pxb,
                                  (l == 1) ? out : nullptr, skip, ln_g, ln_b, l);
    }
}